// round 2
// baseline (speedup 1.0000x reference)
#include <cuda_runtime.h>

#define NB      64
#define NT      1024
#define MAXLAG  256
#define NCHUNK  8

__device__ float g_partial[NB * MAXLAG * NCHUNK];
__device__ float g_pt[NB];

// lengths may arrive as int64 or int32 depending on jax x64 config.
// Values are in [512, 1024], so for int64 little-endian layout word[1]
// (high half of element 0) is 0; for int32 word[1] is lengths[1] >= 512.
__device__ __forceinline__ int load_length(const unsigned int* lp, int b) {
    bool is64 = (lp[1] == 0u);
    return is64 ? (int)lp[2 * b] : (int)lp[b];
}

__global__ __launch_bounds__(256)
void msd_partial_kernel(const float2* __restrict__ traj,
                        const unsigned int* __restrict__ lens)
{
    __shared__ float2 s[NT];
    const int b   = blockIdx.x;
    const int c   = blockIdx.y;   // p-chunk
    const int tid = threadIdx.x;

    // Stage trajectory row b into smem (coalesced float4 loads).
    const float4* g4 = (const float4*)(traj + (size_t)b * NT);
    float4* s4 = (float4*)s;
    #pragma unroll
    for (int i = 0; i < NT / 2 / 256; ++i)
        s4[tid + i * 256] = g4[tid + i * 256];
    __syncthreads();

    const int L = load_length(lens, b);
    const int l = tid + 1;
    const int n = L - l;          // count of valid start positions (<= T-1)

    float acc = 0.f;
    #pragma unroll 4
    for (int p = c; p < n; p += NCHUNK) {
        float2 a = s[p];          // broadcast across warp
        float2 e = s[p + l];      // consecutive -> conflict-free
        float dx = e.x - a.x;
        float dy = e.y - a.y;
        acc = fmaf(dx, dx, acc);
        acc = fmaf(dy, dy, acc);
    }
    g_partial[(b * MAXLAG + tid) * NCHUNK + c] = acc;
}

__device__ __forceinline__ float block_reduce_256(float v, float* wsum, int tid)
{
    #pragma unroll
    for (int o = 16; o > 0; o >>= 1)
        v += __shfl_down_sync(0xFFFFFFFFu, v, o);
    if ((tid & 31) == 0) wsum[tid >> 5] = v;
    __syncthreads();
    float t = (tid < 8) ? wsum[tid] : 0.f;
    if (tid < 8) {
        #pragma unroll
        for (int o = 4; o > 0; o >>= 1)
            t += __shfl_down_sync(0xFFu, t, o);
        if (tid == 0) wsum[0] = t;
    }
    __syncthreads();
    float r = wsum[0];
    __syncthreads();
    return r;
}

__global__ __launch_bounds__(256)
void regress_kernel(const float* __restrict__ alpha_pred,
                    const unsigned int* __restrict__ lens)
{
    __shared__ float wsum[8];
    const int b   = blockIdx.x;
    const int tid = threadIdx.x;
    const int l   = tid + 1;
    const int L   = load_length(lens, b);

    float S = 0.f;
    const float* pp = &g_partial[(b * MAXLAG + tid) * NCHUNK];
    #pragma unroll
    for (int c = 0; c < NCHUNK; ++c) S += pp[c];

    const int   n       = L - l;
    const float cnt     = fmaxf((float)(n > 0 ? n : 0), 1.0f);
    const float msd     = S / cnt;
    const float log_msd = logf(msd + 1e-8f);
    const float mask    = (L > l) ? 1.f : 0.f;
    const float alpha   = alpha_pred[b];
    const float resid   = log_msd - alpha * logf((float)l);

    // denom = sum(lag_mask) = clamp(min(L-1, MAXLAG), >=1); exact, no reduction.
    int   nm    = L - 1; if (nm > MAXLAG) nm = MAXLAG; if (nm < 0) nm = 0;
    const float denom = fmaxf((float)nm, 1.0f);

    const float sum_resid = block_reduce_256(resid * mask, wsum, tid);
    const float intercept = sum_resid / denom;

    const float err   = resid - intercept;
    const float sqerr = block_reduce_256(mask * err * err, wsum, tid);

    if (tid == 0) g_pt[b] = sqerr / denom;
}

__global__ void final_kernel(float* __restrict__ out)
{
    __shared__ float ws[2];
    const int tid = threadIdx.x;   // 64 threads
    float v = g_pt[tid];
    #pragma unroll
    for (int o = 16; o > 0; o >>= 1)
        v += __shfl_down_sync(0xFFFFFFFFu, v, o);
    if ((tid & 31) == 0) ws[tid >> 5] = v;
    __syncthreads();
    if (tid == 0) out[0] = (ws[0] + ws[1]) * (1.0f / (float)NB);
}

extern "C" void kernel_launch(void* const* d_in, const int* in_sizes, int n_in,
                              void* d_out, int out_size)
{
    const float*        alpha = (const float*)d_in[0];
    const float2*       traj  = (const float2*)d_in[1];
    const unsigned int* lens  = (const unsigned int*)d_in[2];
    float*              out   = (float*)d_out;

    msd_partial_kernel<<<dim3(NB, NCHUNK), 256>>>(traj, lens);
    regress_kernel<<<NB, 256>>>(alpha, lens);
    final_kernel<<<1, 64>>>(out);
}

// round 3
// speedup vs baseline: 1.1553x; 1.1553x over previous
#include <cuda_runtime.h>

#define NB      64
#define NT      1024
#define MAXLAG  256
#define NCHUNK  16

__device__ float        g_partial[NCHUNK * NB * MAXLAG];
__device__ float        g_pt[NB];
__device__ unsigned int g_cnt[NB];      // zero-initialized; reset by last observer
__device__ unsigned int g_cnt2;         // zero-initialized; reset by last observer

// lengths may arrive as int64 or int32 depending on jax x64 config.
// Values are in [512, 1024]; for little-endian int64 layout word[1] (high half
// of element 0) is 0, for int32 word[1] is lengths[1] >= 512.
__device__ __forceinline__ int load_length(const unsigned int* lp, int b) {
    bool is64 = (lp[1] == 0u);
    return is64 ? (int)lp[2 * b] : (int)lp[b];
}

__device__ __forceinline__ float block_reduce_256(float v, float* wsum, int tid)
{
    #pragma unroll
    for (int o = 16; o > 0; o >>= 1)
        v += __shfl_down_sync(0xFFFFFFFFu, v, o);
    if ((tid & 31) == 0) wsum[tid >> 5] = v;
    __syncthreads();
    float t = (tid < 8) ? wsum[tid] : 0.f;
    if (tid < 8) {
        #pragma unroll
        for (int o = 4; o > 0; o >>= 1)
            t += __shfl_down_sync(0xFFu, t, o);
        if (tid == 0) wsum[0] = t;
    }
    __syncthreads();
    float r = wsum[0];
    __syncthreads();
    return r;
}

__global__ __launch_bounds__(256)
void physics_loss_fused(const float* __restrict__ alpha_pred,
                        const float2* __restrict__ traj,
                        const unsigned int* __restrict__ lens,
                        float* __restrict__ out)
{
    __shared__ float2 s[NT];
    __shared__ float  wsum[8];
    __shared__ unsigned int s_flag;

    const int b   = blockIdx.x;
    const int c   = blockIdx.y;   // p-chunk
    const int tid = threadIdx.x;

    // ---- Stage trajectory row b into smem (coalesced float4 loads) ----
    {
        const float4* g4 = (const float4*)(traj + (size_t)b * NT);
        float4* s4 = (float4*)s;
        s4[tid]       = g4[tid];
        s4[tid + 256] = g4[tid + 256];
    }
    __syncthreads();

    const int L = load_length(lens, b);
    const int l = tid + 1;
    const int n = L - l;          // # valid start positions for this lag

    // ---- MSD partial accumulation (lag = tid, positions strided by NCHUNK) ----
    float acc = 0.f;
    #pragma unroll 4
    for (int p = c; p < n; p += NCHUNK) {
        float2 a = s[p];          // uniform across warp -> broadcast
        float2 e = s[p + l];      // consecutive lanes -> conflict-free
        float dx = e.x - a.x;
        float dy = e.y - a.y;
        acc = fmaf(dx, dx, acc);
        acc = fmaf(dy, dy, acc);
    }
    g_partial[(c * NB + b) * MAXLAG + tid] = acc;   // coalesced

    // ---- Last chunk-block of batch b performs the regression ----
    __threadfence();
    if (tid == 0) {
        unsigned int old = atomicAdd(&g_cnt[b], 1u);
        s_flag = (old == NCHUNK - 1) ? 1u : 0u;
        if (s_flag) g_cnt[b] = 0u;                  // reset for next graph replay
    }
    __syncthreads();
    if (!s_flag) return;

    float S = 0.f;
    #pragma unroll
    for (int cc = 0; cc < NCHUNK; ++cc)
        S += __ldcg(&g_partial[(cc * NB + b) * MAXLAG + tid]);

    const float cnt     = fmaxf((float)(n > 0 ? n : 0), 1.0f);
    const float msd     = S / cnt;
    const float log_msd = logf(msd + 1e-8f);
    const float mask    = (L > l) ? 1.f : 0.f;
    const float alpha   = alpha_pred[b];
    const float resid   = log_msd - alpha * logf((float)l);

    // denom = sum(lag_mask) = clamp(min(L-1, MAXLAG), >=1); exact closed form.
    int nm = L - 1; if (nm > MAXLAG) nm = MAXLAG; if (nm < 0) nm = 0;
    const float denom = fmaxf((float)nm, 1.0f);

    const float sum_resid = block_reduce_256(resid * mask, wsum, tid);
    const float intercept = sum_resid / denom;

    const float err   = resid - intercept;
    const float sqerr = block_reduce_256(mask * err * err, wsum, tid);

    // ---- Last regression block performs the final mean ----
    if (tid == 0) {
        g_pt[b] = sqerr / denom;
        __threadfence();
        unsigned int old2 = atomicAdd(&g_cnt2, 1u);
        s_flag = (old2 == NB - 1) ? 1u : 0u;
        if (s_flag) g_cnt2 = 0u;                    // reset for next graph replay
    }
    __syncthreads();
    if (!s_flag) return;

    // Fixed-order final reduction over 64 per-trajectory values (deterministic).
    float v = (tid < NB) ? __ldcg(&g_pt[tid]) : 0.f;
    const float total = block_reduce_256(v, wsum, tid);
    if (tid == 0) out[0] = total * (1.0f / (float)NB);
}

extern "C" void kernel_launch(void* const* d_in, const int* in_sizes, int n_in,
                              void* d_out, int out_size)
{
    const float*        alpha = (const float*)d_in[0];
    const float2*       traj  = (const float2*)d_in[1];
    const unsigned int* lens  = (const unsigned int*)d_in[2];
    float*              out   = (float*)d_out;

    physics_loss_fused<<<dim3(NB, NCHUNK), 256>>>(alpha, traj, lens, out);
}

// round 4
// speedup vs baseline: 1.3290x; 1.1503x over previous
#include <cuda_runtime.h>

#define NB      64
#define NT      1024
#define MAXLAG  256
#define CBLK    8                    // blocks per batch
#define NWARP   8                    // warps per block
#define NCHUNKS (CBLK * NWARP)       // 64 position chunks per batch
#define CHUNKP  16                   // positions per chunk (4 steps x 4)
#define SPAD    1536                 // padded smem float2 elements

typedef unsigned long long ull;

__device__ float        g_partial[NB * NCHUNKS * MAXLAG];   // [b][chunk][lag]
__device__ float        g_pt[NB];
__device__ unsigned int g_cnt[NB];   // zero-init; reset by last observer
__device__ unsigned int g_cnt2;      // zero-init; reset by last observer

// lengths may arrive as int64 or int32 (jax x64 config). Values in [512,1024];
// little-endian int64 => word[1] (high half of elem 0) == 0.
__device__ __forceinline__ int load_length(const unsigned int* lp, int b) {
    bool is64 = (lp[1] == 0u);
    return is64 ? (int)lp[2 * b] : (int)lp[b];
}

// XOR swizzle on float2 index: spreads lane-stride-8 accesses conflict-free.
__device__ __forceinline__ int swz(int q) { return q ^ ((q >> 4) & 15); }

__device__ __forceinline__ ull fma2(ull a, ull b, ull c) {
    ull r;
    asm("fma.rn.f32x2 %0, %1, %2, %3;" : "=l"(r) : "l"(a), "l"(b), "l"(c));
    return r;
}

__device__ __forceinline__ float block_reduce_256(float v, float* wsum, int tid)
{
    #pragma unroll
    for (int o = 16; o > 0; o >>= 1)
        v += __shfl_down_sync(0xFFFFFFFFu, v, o);
    if ((tid & 31) == 0) wsum[tid >> 5] = v;
    __syncthreads();
    float t = (tid < 8) ? wsum[tid] : 0.f;
    if (tid < 8) {
        #pragma unroll
        for (int o = 4; o > 0; o >>= 1)
            t += __shfl_down_sync(0xFFu, t, o);
        if (tid == 0) wsum[0] = t;
    }
    __syncthreads();
    float r = wsum[0];
    __syncthreads();
    return r;
}

__global__ __launch_bounds__(256)
void physics_loss_fused(const float* __restrict__ alpha_pred,
                        const ull* __restrict__ traj,     // float2 as u64
                        const unsigned int* __restrict__ lens,
                        float* __restrict__ out)
{
    __shared__ ull sx[SPAD];                 // swizzled trajectory row (padded)
    __shared__ float wsum[8];
    __shared__ unsigned int s_flag;

    const int b    = blockIdx.x;
    const int cb   = blockIdx.y;
    const int tid  = threadIdx.x;
    const int lane = tid & 31;
    const int warp = tid >> 5;

    // ---- Stage row b into swizzled smem (coalesced LDG.64) ----
    {
        const ull* g = traj + (size_t)b * NT;
        #pragma unroll
        for (int k = 0; k < NT / 256; ++k) {
            int idx = tid + 256 * k;
            sx[swz(idx)] = g[idx];
        }
    }
    __syncthreads();

    const int L = load_length(lens, b);

    // ---- Register-tiled MSD: thread = 8 consecutive lags, 16 positions ----
    const int chunk = cb * NWARP + warp;        // 0..63
    const int p0    = chunk * CHUNKP;
    const int lt1   = 8 * lane + 1;             // first lag value of this thread
    const int base  = p0 + lt1;                 // q of pair (i=0, j=0)

    const ull NEG1 = 0xBF800000BF800000ull;
    ull w[23];
    ull acc[8] = {0, 0, 0, 0, 0, 0, 0, 0};

    #pragma unroll
    for (int k = 0; k < 11; ++k) w[k] = sx[swz(base + k)];

    #pragma unroll
    for (int s = 0; s < 4; ++s) {
        if (s > 0) {
            #pragma unroll
            for (int k = 0; k < 4; ++k)
                w[4 * s + 7 + k] = sx[swz(base + 4 * s + 7 + k)];
        }
        const int p   = p0 + 4 * s;
        const int kth = L - (p + lt1);          // pair (i,j) valid iff i+j < kth
        if (kth > 0) {
            ull a0 = sx[swz(p + 0)];            // warp-uniform -> broadcast
            ull a1 = sx[swz(p + 1)];
            ull a2 = sx[swz(p + 2)];
            ull a3 = sx[swz(p + 3)];
            if (kth > 10) {                     // fully valid step
                #pragma unroll
                for (int j = 0; j < 8; ++j) {
                    ull d;
                    d = fma2(a0, NEG1, w[4 * s + 0 + j]); acc[j] = fma2(d, d, acc[j]);
                    d = fma2(a1, NEG1, w[4 * s + 1 + j]); acc[j] = fma2(d, d, acc[j]);
                    d = fma2(a2, NEG1, w[4 * s + 2 + j]); acc[j] = fma2(d, d, acc[j]);
                    d = fma2(a3, NEG1, w[4 * s + 3 + j]); acc[j] = fma2(d, d, acc[j]);
                }
            } else {                            // ragged boundary step
                const ull av[4] = {a0, a1, a2, a3};
                #pragma unroll
                for (int j = 0; j < 8; ++j) {
                    #pragma unroll
                    for (int i = 0; i < 4; ++i) {
                        if (i + j < kth) {
                            ull d = fma2(av[i], NEG1, w[4 * s + i + j]);
                            acc[j] = fma2(d, d, acc[j]);
                        }
                    }
                }
            }
        }
    }

    // ---- Write per-chunk partials: lane covers lags 8*lane..8*lane+7 ----
    {
        float r[8];
        #pragma unroll
        for (int j = 0; j < 8; ++j) {
            float2 v = *(float2*)&acc[j];
            r[j] = v.x + v.y;
        }
        float* dst = &g_partial[((size_t)b * NCHUNKS + chunk) * MAXLAG + 8 * lane];
        ((float4*)dst)[0] = make_float4(r[0], r[1], r[2], r[3]);
        ((float4*)dst)[1] = make_float4(r[4], r[5], r[6], r[7]);
    }

    // ---- Last block of batch b performs the regression ----
    __threadfence();
    if (tid == 0) {
        unsigned int old = atomicAdd(&g_cnt[b], 1u);
        s_flag = (old == CBLK - 1) ? 1u : 0u;
        if (s_flag) g_cnt[b] = 0u;              // reset for graph replay
    }
    __syncthreads();
    if (!s_flag) return;

    // Sum 64 chunk partials for this lag (tid = lag index)
    float S0 = 0.f, S1 = 0.f, S2 = 0.f, S3 = 0.f;
    {
        const float* pp = &g_partial[(size_t)b * NCHUNKS * MAXLAG + tid];
        #pragma unroll
        for (int cc = 0; cc < NCHUNKS; cc += 4) {
            S0 += __ldcg(&pp[(cc + 0) * MAXLAG]);
            S1 += __ldcg(&pp[(cc + 1) * MAXLAG]);
            S2 += __ldcg(&pp[(cc + 2) * MAXLAG]);
            S3 += __ldcg(&pp[(cc + 3) * MAXLAG]);
        }
    }
    const float S = (S0 + S1) + (S2 + S3);

    const int   l       = tid + 1;
    const int   n       = L - l;
    const float cnt     = fmaxf((float)(n > 0 ? n : 0), 1.0f);
    const float msd     = S / cnt;
    const float log_msd = logf(msd + 1e-8f);
    const float mask    = (L > l) ? 1.f : 0.f;
    const float alpha   = alpha_pred[b];
    const float resid   = log_msd - alpha * logf((float)l);

    int nm = L - 1; if (nm > MAXLAG) nm = MAXLAG; if (nm < 0) nm = 0;
    const float denom = fmaxf((float)nm, 1.0f);

    const float sum_resid = block_reduce_256(resid * mask, wsum, tid);
    const float intercept = sum_resid / denom;

    const float err   = resid - intercept;
    const float sqerr = block_reduce_256(mask * err * err, wsum, tid);

    // ---- Last regression block performs the final mean ----
    if (tid == 0) {
        g_pt[b] = sqerr / denom;
        __threadfence();
        unsigned int old2 = atomicAdd(&g_cnt2, 1u);
        s_flag = (old2 == NB - 1) ? 1u : 0u;
        if (s_flag) g_cnt2 = 0u;                // reset for graph replay
    }
    __syncthreads();
    if (!s_flag) return;

    float v = (tid < NB) ? __ldcg(&g_pt[tid]) : 0.f;
    const float total = block_reduce_256(v, wsum, tid);
    if (tid == 0) out[0] = total * (1.0f / (float)NB);
}

extern "C" void kernel_launch(void* const* d_in, const int* in_sizes, int n_in,
                              void* d_out, int out_size)
{
    const float*        alpha = (const float*)d_in[0];
    const ull*          traj  = (const ull*)d_in[1];
    const unsigned int* lens  = (const unsigned int*)d_in[2];
    float*              out   = (float*)d_out;

    physics_loss_fused<<<dim3(NB, CBLK), 256>>>(alpha, traj, lens, out);
}

// round 9
// speedup vs baseline: 1.4663x; 1.1034x over previous
#include <cuda_runtime.h>

#define NB      64
#define NT      1024
#define MAXLAG  256
#define CBLK    16                   // blocks per batch
#define NWARP   8                    // warps per block
#define CHUNKP  8                    // positions per warp-chunk (2 steps x 4)
#define BLKP    (NWARP * CHUNKP)     // 64 positions per block
#define SWIN    320                  // staged window (float2): 64 + 255 + 1

typedef unsigned long long ull;

__device__ float        g_partial[NB * CBLK * MAXLAG];   // [b][cb][lag]
__device__ float        g_pt[NB];
__device__ unsigned int g_cnt[NB];   // zero-init; reset by last observer
__device__ unsigned int g_cnt2;      // zero-init; reset by last observer

// lengths may arrive as int64 or int32 (jax x64 config). Values in [512,1024];
// little-endian int64 => word[1] (high half of elem 0) == 0.
__device__ __forceinline__ int load_length(const unsigned int* lp, int b) {
    bool is64 = (lp[1] == 0u);
    return is64 ? (int)lp[2 * b] : (int)lp[b];
}

// XOR swizzle on float2 index (modifies low 4 bits only; stays in 16-group).
__device__ __forceinline__ int swz(int q) { return q ^ ((q >> 4) & 15); }

__device__ __forceinline__ ull fma2(ull a, ull b, ull c) {
    ull r;
    asm("fma.rn.f32x2 %0, %1, %2, %3;" : "=l"(r) : "l"(a), "l"(b), "l"(c));
    return r;
}

__device__ __forceinline__ float block_reduce_256(float v, float* wsum, int tid)
{
    #pragma unroll
    for (int o = 16; o > 0; o >>= 1)
        v += __shfl_down_sync(0xFFFFFFFFu, v, o);
    if ((tid & 31) == 0) wsum[tid >> 5] = v;
    __syncthreads();
    float t = (tid < 8) ? wsum[tid] : 0.f;
    if (tid < 8) {
        #pragma unroll
        for (int o = 4; o > 0; o >>= 1)
            t += __shfl_down_sync(0xFFu, t, o);
        if (tid == 0) wsum[0] = t;
    }
    __syncthreads();
    float r = wsum[0];
    __syncthreads();
    return r;
}

__global__ __launch_bounds__(256, 4)
void physics_loss_fused(const float* __restrict__ alpha_pred,
                        const ull* __restrict__ traj,     // float2 as u64
                        const unsigned int* __restrict__ lens,
                        float* __restrict__ out)
{
    __shared__ ull   sx[SWIN];                 // swizzled window
    __shared__ float sred[NWARP][MAXLAG];      // per-warp lag partials
    __shared__ float wsum[8];
    __shared__ unsigned int s_flag;

    const int b    = blockIdx.x;
    const int cb   = blockIdx.y;
    const int tid  = threadIdx.x;
    const int lane = tid & 31;
    const int warp = tid >> 5;
    const int P0   = cb * BLKP;                // block's first position

    // ---- Stage window [P0, P0+SWIN) of row b (clamped; OOB is masked) ----
    {
        const ull* g = traj + (size_t)b * NT;
        int i0 = P0 + tid;
        sx[swz(tid)] = g[i0 < NT ? i0 : NT - 1];
        if (tid < SWIN - 256) {
            int i1 = P0 + tid + 256;
            sx[swz(tid + 256)] = g[i1 < NT ? i1 : NT - 1];
        }
    }
    __syncthreads();

    const int L = load_length(lens, b);

    // ---- Register-tiled MSD: thread = 8 lags x 8 positions ----
    const int pw   = warp * CHUNKP;            // warp's first position (local)
    const int lt1  = 8 * lane + 1;             // first lag of this thread
    const int base = pw + lt1;                 // local idx of pair (0,0) endpoint

    const ull NEG1 = 0xBF800000BF800000ull;
    ull w[15];
    ull acc[8] = {0, 0, 0, 0, 0, 0, 0, 0};

    #pragma unroll
    for (int k = 0; k < 11; ++k) w[k] = sx[swz(base + k)];

    #pragma unroll
    for (int s = 0; s < 2; ++s) {
        if (s > 0) {
            #pragma unroll
            for (int k = 0; k < 4; ++k)
                w[11 + k] = sx[swz(base + 11 + k)];
        }
        const int pl  = pw + 4 * s;            // local position of i=0
        const int kth = L - (P0 + pl + lt1);   // pair (i,j) valid iff i+j < kth
        if (kth > 0) {
            ull a0 = sx[swz(pl + 0)];          // warp-uniform -> broadcast
            ull a1 = sx[swz(pl + 1)];
            ull a2 = sx[swz(pl + 2)];
            ull a3 = sx[swz(pl + 3)];
            if (kth > 10) {                    // fully valid step
                #pragma unroll
                for (int j = 0; j < 8; ++j) {
                    ull d;
                    d = fma2(a0, NEG1, w[4 * s + 0 + j]); acc[j] = fma2(d, d, acc[j]);
                    d = fma2(a1, NEG1, w[4 * s + 1 + j]); acc[j] = fma2(d, d, acc[j]);
                    d = fma2(a2, NEG1, w[4 * s + 2 + j]); acc[j] = fma2(d, d, acc[j]);
                    d = fma2(a3, NEG1, w[4 * s + 3 + j]); acc[j] = fma2(d, d, acc[j]);
                }
            } else {                           // ragged boundary step
                const ull av[4] = {a0, a1, a2, a3};
                #pragma unroll
                for (int j = 0; j < 8; ++j) {
                    #pragma unroll
                    for (int i = 0; i < 4; ++i) {
                        if (i + j < kth) {
                            ull d = fma2(av[i], NEG1, w[4 * s + i + j]);
                            acc[j] = fma2(d, d, acc[j]);
                        }
                    }
                }
            }
        }
    }

    // ---- Cross-warp reduction in smem: one partial per lag per block ----
    {
        float r[8];
        #pragma unroll
        for (int j = 0; j < 8; ++j) {
            float2 v = *(float2*)&acc[j];
            r[j] = v.x + v.y;
        }
        float* row = &sred[warp][8 * lane];
        ((float4*)row)[0] = make_float4(r[0], r[1], r[2], r[3]);
        ((float4*)row)[1] = make_float4(r[4], r[5], r[6], r[7]);
    }
    __syncthreads();
    {
        float t = 0.f;
        #pragma unroll
        for (int ww = 0; ww < NWARP; ++ww) t += sred[ww][tid];
        g_partial[((size_t)b * CBLK + cb) * MAXLAG + tid] = t;   // coalesced
    }

    // ---- Last block of batch b performs the regression ----
    __threadfence();
    if (tid == 0) {
        unsigned int old = atomicAdd(&g_cnt[b], 1u);
        s_flag = (old == CBLK - 1) ? 1u : 0u;
        if (s_flag) g_cnt[b] = 0u;             // reset for graph replay
    }
    __syncthreads();
    if (!s_flag) return;

    float S0 = 0.f, S1 = 0.f, S2 = 0.f, S3 = 0.f;
    {
        const float* pp = &g_partial[(size_t)b * CBLK * MAXLAG + tid];
        #pragma unroll
        for (int cc = 0; cc < CBLK; cc += 4) {
            S0 += __ldcg(&pp[(cc + 0) * MAXLAG]);
            S1 += __ldcg(&pp[(cc + 1) * MAXLAG]);
            S2 += __ldcg(&pp[(cc + 2) * MAXLAG]);
            S3 += __ldcg(&pp[(cc + 3) * MAXLAG]);
        }
    }
    const float S = (S0 + S1) + (S2 + S3);

    const int   l       = tid + 1;
    const int   n       = L - l;
    const float cnt     = fmaxf((float)(n > 0 ? n : 0), 1.0f);
    const float msd     = S / cnt;
    const float log_msd = logf(msd + 1e-8f);
    const float mask    = (L > l) ? 1.f : 0.f;
    const float alpha   = alpha_pred[b];
    const float resid   = log_msd - alpha * logf((float)l);

    int nm = L - 1; if (nm > MAXLAG) nm = MAXLAG; if (nm < 0) nm = 0;
    const float denom = fmaxf((float)nm, 1.0f);

    const float sum_resid = block_reduce_256(resid * mask, wsum, tid);
    const float intercept = sum_resid / denom;

    const float err   = resid - intercept;
    const float sqerr = block_reduce_256(mask * err * err, wsum, tid);

    // ---- Last regression block performs the final mean ----
    if (tid == 0) {
        g_pt[b] = sqerr / denom;
        __threadfence();
        unsigned int old2 = atomicAdd(&g_cnt2, 1u);
        s_flag = (old2 == NB - 1) ? 1u : 0u;
        if (s_flag) g_cnt2 = 0u;               // reset for graph replay
    }
    __syncthreads();
    if (!s_flag) return;

    float v = (tid < NB) ? __ldcg(&g_pt[tid]) : 0.f;
    const float total = block_reduce_256(v, wsum, tid);
    if (tid == 0) out[0] = total * (1.0f / (float)NB);
}

extern "C" void kernel_launch(void* const* d_in, const int* in_sizes, int n_in,
                              void* d_out, int out_size)
{
    const float*        alpha = (const float*)d_in[0];
    const ull*          traj  = (const ull*)d_in[1];
    const unsigned int* lens  = (const unsigned int*)d_in[2];
    float*              out   = (float*)d_out;

    physics_loss_fused<<<dim3(NB, CBLK), 256>>>(alpha, traj, lens, out);
}